// round 1
// baseline (speedup 1.0000x reference)
#include <cuda_runtime.h>
#include <cuda_bf16.h>
#include <math.h>

// Problem constants
#define BZ   128
#define T_   32
#define D_   768
#define DFF_ 3072
#define E_   8
#define BEAMS_ 2
#define NROWS (BZ * BEAMS_)          // 256
#define OUT_ELEMS ((size_t)NROWS * T_ * D_)   // 6,291,456

// Scratch: h = gelu(x @ W1 + b1), 256 x 32 x 3072 fp32 = ~100 MB
__device__ float g_h[(size_t)NROWS * T_ * DFF_];
// Per-row expert selection
__device__ int g_sel[NROWS];

// ---------------------------------------------------------------------------
// Gating: mean-pool over T, logits = avg @ Wg, softmax, top-2 (stable ties)
// One block per batch element. 256 threads.
// ---------------------------------------------------------------------------
__global__ void gate_kernel(const float* __restrict__ x,
                            const float* __restrict__ Wg,
                            float* __restrict__ out, int out_size)
{
    const int b = blockIdx.x;        // 0..127
    const int t = threadIdx.x;       // 0..255
    __shared__ float s_avg[D_];
    __shared__ float s_logits[E_];

    const float* xb = x + (size_t)b * T_ * D_;
    for (int d = t; d < D_; d += 256) {
        float s = 0.f;
        #pragma unroll
        for (int tt = 0; tt < T_; tt++) s += xb[tt * D_ + d];
        s_avg[d] = s * (1.0f / (float)T_);
    }
    __syncthreads();

    // 8 warps: warp w computes logit for expert w
    const int w = t >> 5, lane = t & 31;
    float p = 0.f;
    for (int d = lane; d < D_; d += 32) p += s_avg[d] * Wg[d * E_ + w];
    #pragma unroll
    for (int o = 16; o; o >>= 1) p += __shfl_xor_sync(0xffffffffu, p, o);
    if (lane == 0) s_logits[w] = p;
    __syncthreads();

    if (t == 0) {
        float mx = s_logits[0];
        #pragma unroll
        for (int e = 1; e < E_; e++) mx = fmaxf(mx, s_logits[e]);
        float pr[E_]; float se = 0.f;
        #pragma unroll
        for (int e = 0; e < E_; e++) { pr[e] = expf(s_logits[e] - mx); se += pr[e]; }
        float inv = 1.0f / se;
        #pragma unroll
        for (int e = 0; e < E_; e++) pr[e] *= inv;

        // top-2, ties -> lower index first (matches jax.lax.top_k)
        int i1 = 0;
        #pragma unroll
        for (int e = 1; e < E_; e++) if (pr[e] > pr[i1]) i1 = e;
        int i2 = -1;
        #pragma unroll
        for (int e = 0; e < E_; e++) {
            if (e == i1) continue;
            if (i2 < 0 || pr[e] > pr[i2]) i2 = e;
        }

        g_sel[2 * b + 0] = i1;
        g_sel[2 * b + 1] = i2;

        if (out_size >= (int)(OUT_ELEMS + 2 * NROWS)) {
            out[OUT_ELEMS + 2 * b + 0] = pr[i1];
            out[OUT_ELEMS + 2 * b + 1] = pr[i2];
            out[OUT_ELEMS + NROWS + 2 * b + 0] = (float)i1;
            out[OUT_ELEMS + NROWS + 2 * b + 1] = (float)i2;
        }
    }
}

// ---------------------------------------------------------------------------
// Tiled fp32 GEMM: per block computes a 32 x 128 tile of
//   O[n] = act( A[n] @ W[sel(n)] + bias[sel(n)] )
// BM=32 (fixed), BN=128, BK=32, 128 threads, 4x8 per-thread micro-tile.
// ---------------------------------------------------------------------------
__device__ __forceinline__ float gelu_exact(float v) {
    return 0.5f * v * (1.0f + erff(v * 0.70710678118654752f));
}

template <int KDIM, int NDIM, bool GELU, bool HALFN, bool OUT_IS_GH, bool IN_IS_GH>
__global__ __launch_bounds__(128)
void gemm_kernel(const float* __restrict__ Aarg,
                 const float* __restrict__ Wbase,
                 const float* __restrict__ Bbase,
                 float* __restrict__ Oarg)
{
    const int n     = blockIdx.x;   // row 0..255
    const int ntile = blockIdx.y;   // column tile
    const int e     = g_sel[n];

    const float* A0 = IN_IS_GH ? g_h : Aarg;
    float*       O0 = OUT_IS_GH ? g_h : Oarg;

    const float* A    = A0 + (size_t)(HALFN ? (n >> 1) : n) * T_ * KDIM;
    const float* W    = Wbase + (size_t)e * KDIM * NDIM + (size_t)ntile * 128;
    const float* bias = Bbase + (size_t)e * NDIM + (size_t)ntile * 128;
    float*       O    = O0 + (size_t)n * T_ * NDIM + (size_t)ntile * 128;

    __shared__ float As[32][32];    // [k][m] transposed
    __shared__ float Bs[32][128];   // [k][j]

    const int t  = threadIdx.x;     // 0..127
    const int ty = t >> 4;          // 0..7  -> rows ty*4 .. ty*4+3
    const int tx = t & 15;          // 0..15 -> cols tx*8 .. tx*8+7

    float acc[4][8];
    #pragma unroll
    for (int i = 0; i < 4; i++)
        #pragma unroll
        for (int j = 0; j < 8; j++) acc[i][j] = 0.f;

    for (int k0 = 0; k0 < KDIM; k0 += 32) {
        // Load A tile: 32 rows x 32 k, vectorized along k, stored transposed
        #pragma unroll
        for (int i = 0; i < 2; i++) {
            int lin = t + i * 128;          // 0..255
            int m  = lin >> 3;              // 0..31
            int kq = lin & 7;               // 0..7 (float4 index)
            float4 v = *(const float4*)(A + (size_t)m * KDIM + k0 + kq * 4);
            As[kq * 4 + 0][m] = v.x;
            As[kq * 4 + 1][m] = v.y;
            As[kq * 4 + 2][m] = v.z;
            As[kq * 4 + 3][m] = v.w;
        }
        // Load B tile: 32 k-rows x 128 cols
        #pragma unroll
        for (int i = 0; i < 8; i++) {
            int lin = t + i * 128;          // 0..1023 (float4 units)
            int kk = lin >> 5;              // 0..31
            int jq = lin & 31;              // 0..31
            *(float4*)&Bs[kk][jq * 4] =
                *(const float4*)(W + (size_t)(k0 + kk) * NDIM + jq * 4);
        }
        __syncthreads();

        #pragma unroll
        for (int k = 0; k < 32; k++) {
            float4 a  = *(const float4*)&As[k][ty * 4];
            float4 b0 = *(const float4*)&Bs[k][tx * 8];
            float4 b1 = *(const float4*)&Bs[k][tx * 8 + 4];
            float av[4] = {a.x, a.y, a.z, a.w};
            float bv[8] = {b0.x, b0.y, b0.z, b0.w, b1.x, b1.y, b1.z, b1.w};
            #pragma unroll
            for (int i = 0; i < 4; i++)
                #pragma unroll
                for (int j = 0; j < 8; j++)
                    acc[i][j] = fmaf(av[i], bv[j], acc[i][j]);
        }
        __syncthreads();
    }

    // Epilogue: bias (+ optional exact GELU), write out
    #pragma unroll
    for (int i = 0; i < 4; i++) {
        int m = ty * 4 + i;
        #pragma unroll
        for (int j = 0; j < 8; j++) {
            int c = tx * 8 + j;
            float v = acc[i][j] + bias[c];
            if (GELU) v = gelu_exact(v);
            O[(size_t)m * NDIM + c] = v;
        }
    }
}

// ---------------------------------------------------------------------------
// Launch
// ---------------------------------------------------------------------------
extern "C" void kernel_launch(void* const* d_in, const int* in_sizes, int n_in,
                              void* d_out, int out_size)
{
    const float* x  = (const float*)d_in[0];
    // d_in[1] = attention_mask (reference overrides it with ones; unused)
    const float* Wg = (const float*)d_in[2];
    const float* W1 = (const float*)d_in[3];
    const float* b1 = (const float*)d_in[4];
    const float* W2 = (const float*)d_in[5];
    const float* b2 = (const float*)d_in[6];
    float* out = (float*)d_out;

    // 1) Gating: routing decisions + beam_scores / expert_route outputs
    gate_kernel<<<BZ, 256>>>(x, Wg, out, out_size);

    // 2) h = gelu(x[n/2] @ W1[sel] + b1[sel])   -> g_h
    //    grid: x = row (fast) so each wave shares W column-slices via L2
    gemm_kernel<D_, DFF_, true, true, true, false>
        <<<dim3(NROWS, DFF_ / 128), 128>>>(x, W1, b1, out /*unused*/);

    // 3) out = h @ W2[sel] + b2[sel]
    gemm_kernel<DFF_, D_, false, false, false, true>
        <<<dim3(NROWS, D_ / 128), 128>>>(x /*unused*/, W2, b2, out);
}

// round 3
// speedup vs baseline: 3.9284x; 3.9284x over previous
#include <cuda_runtime.h>
#include <cuda_bf16.h>
#include <math.h>

// Problem constants
#define BZ   128
#define T_   32
#define D_   768
#define DFF_ 3072
#define E_   8
#define BEAMS_ 2
#define NROWS (BZ * BEAMS_)                    // 256
#define OUT_ELEMS ((size_t)NROWS * T_ * D_)    // 6,291,456

// Scratch: h = gelu(x @ W1 + b1), 256 x 32 x 3072 fp32 = ~100 MB
__device__ float g_h[(size_t)NROWS * T_ * DFF_];
// Routing state
__device__ int g_sel[NROWS];
__device__ int g_cnt[E_];
__device__ int g_rows[E_][NROWS];

// ---------------------------------------------------------------------------
// Gating: mean-pool over T, logits = avg @ Wg, softmax, top-2 (stable ties)
// ---------------------------------------------------------------------------
__global__ void gate_kernel(const float* __restrict__ x,
                            const float* __restrict__ Wg,
                            float* __restrict__ out, int out_size)
{
    const int b = blockIdx.x;        // 0..127
    const int t = threadIdx.x;       // 0..255
    __shared__ float s_avg[D_];
    __shared__ float s_logits[E_];

    const float* xb = x + (size_t)b * T_ * D_;
    for (int d = t; d < D_; d += 256) {
        float s = 0.f;
        #pragma unroll
        for (int tt = 0; tt < T_; tt++) s += xb[tt * D_ + d];
        s_avg[d] = s * (1.0f / (float)T_);
    }
    __syncthreads();

    const int w = t >> 5, lane = t & 31;
    float p = 0.f;
    for (int d = lane; d < D_; d += 32) p += s_avg[d] * Wg[d * E_ + w];
    #pragma unroll
    for (int o = 16; o; o >>= 1) p += __shfl_xor_sync(0xffffffffu, p, o);
    if (lane == 0) s_logits[w] = p;
    __syncthreads();

    if (t == 0) {
        float mx = s_logits[0];
        #pragma unroll
        for (int e = 1; e < E_; e++) mx = fmaxf(mx, s_logits[e]);
        float pr[E_]; float se = 0.f;
        #pragma unroll
        for (int e = 0; e < E_; e++) { pr[e] = expf(s_logits[e] - mx); se += pr[e]; }
        float inv = 1.0f / se;
        #pragma unroll
        for (int e = 0; e < E_; e++) pr[e] *= inv;

        int i1 = 0;
        #pragma unroll
        for (int e = 1; e < E_; e++) if (pr[e] > pr[i1]) i1 = e;
        int i2 = -1;
        #pragma unroll
        for (int e = 0; e < E_; e++) {
            if (e == i1) continue;
            if (i2 < 0 || pr[e] > pr[i2]) i2 = e;
        }

        g_sel[2 * b + 0] = i1;
        g_sel[2 * b + 1] = i2;

        if (out_size >= (int)(OUT_ELEMS + 2 * NROWS)) {
            out[OUT_ELEMS + 2 * b + 0] = pr[i1];
            out[OUT_ELEMS + 2 * b + 1] = pr[i2];
            out[OUT_ELEMS + NROWS + 2 * b + 0] = (float)i1;
            out[OUT_ELEMS + NROWS + 2 * b + 1] = (float)i2;
        }
    }
}

// Build per-expert row lists (deterministic, single thread — trivial cost)
__global__ void route_build_kernel()
{
    if (threadIdx.x == 0 && blockIdx.x == 0) {
        int cnt[E_];
        #pragma unroll
        for (int e = 0; e < E_; e++) cnt[e] = 0;
        for (int n = 0; n < NROWS; n++) {
            int e = g_sel[n];
            g_rows[e][cnt[e]++] = n;
        }
        #pragma unroll
        for (int e = 0; e < E_; e++) g_cnt[e] = cnt[e];
    }
}

// ---------------------------------------------------------------------------
// TF32 tensor-core grouped GEMM.
// Per block: 128x128 tile of  O = act(A @ W[e] + b[e])  for expert e.
// M dimension = gathered rows (4 output-rows x 32 tokens).
// 128 threads = 4 warps, each warp owns a 64x64 tile via mma.m16n8k8 tf32.
// Shared memory padded for provably conflict-free fragment loads.
// ---------------------------------------------------------------------------
__device__ __forceinline__ unsigned f2tf(float f) {
    unsigned u;
    asm("cvt.rna.tf32.f32 %0, %1;" : "=r"(u) : "f"(f));
    return u;
}

__device__ __forceinline__ void mma_tf32(float* c, const unsigned* a, const unsigned* b) {
    asm volatile(
        "mma.sync.aligned.m16n8k8.row.col.f32.tf32.tf32.f32 "
        "{%0,%1,%2,%3}, {%4,%5,%6,%7}, {%8,%9}, {%0,%1,%2,%3};"
        : "+f"(c[0]), "+f"(c[1]), "+f"(c[2]), "+f"(c[3])
        : "r"(a[0]), "r"(a[1]), "r"(a[2]), "r"(a[3]), "r"(b[0]), "r"(b[1]));
}

__device__ __forceinline__ float gelu_exact(float v) {
    return 0.5f * v * (1.0f + erff(v * 0.70710678118654752f));
}

template <int KDIM, int NDIM, bool GELU, bool HALF_IN, bool OUT_GH, bool IN_GH>
__global__ __launch_bounds__(128)
void moe_gemm(const float* __restrict__ Aarg,
              const float* __restrict__ Wbase,
              const float* __restrict__ Bbase,
              float* __restrict__ Oarg)
{
    const int e     = blockIdx.z;
    const int cnt   = g_cnt[e];
    const int mtile = blockIdx.y;
    if (mtile * 4 >= cnt) return;           // inactive tile for this expert
    const int ntile = blockIdx.x;

    __shared__ unsigned As[128][36];        // [m][k], pad 36 -> conflict-free frags
    __shared__ unsigned Bs[32][136];        // [k][n], pad 136 -> conflict-free frags
    __shared__ int s_rows[4];

    const int t = threadIdx.x;
    if (t < 4) {
        int idx = mtile * 4 + t;
        s_rows[t] = (idx < cnt) ? g_rows[e][idx] : -1;
    }
    __syncthreads();

    const float* A0   = IN_GH  ? g_h : Aarg;
    const float* W    = Wbase + (size_t)e * KDIM * NDIM + (size_t)ntile * 128;
    const float* bias = Bbase + (size_t)e * NDIM + ntile * 128;

    const int warp = t >> 5, lane = t & 31;
    const int wm = (warp & 1) * 64;         // warp tile m offset
    const int wn = (warp >> 1) * 64;        // warp tile n offset

    float acc[4][8][4];
    #pragma unroll
    for (int i = 0; i < 4; i++)
        #pragma unroll
        for (int j = 0; j < 8; j++)
            #pragma unroll
            for (int q = 0; q < 4; q++) acc[i][j][q] = 0.f;

    // Precompute per-thread A source rows (m fixed per i-step)
    const float* aptr[8];
    #pragma unroll
    for (int i = 0; i < 8; i++) {
        int lin = t + i * 128;              // float4 units, 0..1023
        int m   = lin >> 3;                 // 0..127
        int kq  = lin & 7;                  // 0..7
        int r   = s_rows[m >> 5];
        if (r < 0) r = s_rows[0];           // padded rows read row 0 (valid mem)
        int arow = HALF_IN ? (r >> 1) : r;
        aptr[i] = A0 + ((size_t)arow * T_ + (m & 31)) * (size_t)KDIM + kq * 4;
    }

    for (int k0 = 0; k0 < KDIM; k0 += 32) {
        // --- load A tile 128x32 (cvt to tf32 in smem) ---
        #pragma unroll
        for (int i = 0; i < 8; i++) {
            int lin = t + i * 128;
            int m   = lin >> 3;
            int kq  = lin & 7;
            float4 v = *(const float4*)(aptr[i] + k0);
            uint4 u = make_uint4(f2tf(v.x), f2tf(v.y), f2tf(v.z), f2tf(v.w));
            *(uint4*)&As[m][kq * 4] = u;
        }
        // --- load B tile 32x128 ---
        #pragma unroll
        for (int i = 0; i < 8; i++) {
            int lin = t + i * 128;
            int kk  = lin >> 5;             // 0..31
            int jq  = lin & 31;             // float4 col group
            float4 v = *(const float4*)(W + (size_t)(k0 + kk) * NDIM + jq * 4);
            uint4 u = make_uint4(f2tf(v.x), f2tf(v.y), f2tf(v.z), f2tf(v.w));
            *(uint4*)&Bs[kk][jq * 4] = u;
        }
        __syncthreads();

        // --- 4 k-steps of m16n8k8 ---
        const int ar = lane >> 2, ac = lane & 3;
        #pragma unroll
        for (int ks = 0; ks < 4; ks++) {
            const int kb = ks * 8;
            unsigned a[4][4], b[8][2];
            #pragma unroll
            for (int i = 0; i < 4; i++) {
                int row = wm + i * 16 + ar;
                a[i][0] = As[row][kb + ac];
                a[i][1] = As[row + 8][kb + ac];
                a[i][2] = As[row][kb + ac + 4];
                a[i][3] = As[row + 8][kb + ac + 4];
            }
            #pragma unroll
            for (int j = 0; j < 8; j++) {
                int col = wn + j * 8 + (lane >> 2);
                b[j][0] = Bs[kb + ac][col];
                b[j][1] = Bs[kb + ac + 4][col];
            }
            #pragma unroll
            for (int i = 0; i < 4; i++)
                #pragma unroll
                for (int j = 0; j < 8; j++)
                    mma_tf32(acc[i][j], a[i], b[j]);
        }
        __syncthreads();
    }

    // --- epilogue: bias (+GELU), scatter to gathered output rows ---
    #pragma unroll
    for (int i = 0; i < 4; i++) {
        int r0 = wm + i * 16 + (lane >> 2);
        #pragma unroll
        for (int half = 0; half < 2; half++) {
            int gm   = r0 + half * 8;
            int grow = s_rows[gm >> 5];
            if (grow < 0) continue;          // padded row: no store
            float* orow = (OUT_GH ? g_h : Oarg)
                        + ((size_t)grow * T_ + (gm & 31)) * (size_t)NDIM
                        + (size_t)ntile * 128;
            #pragma unroll
            for (int j = 0; j < 8; j++) {
                int c0 = wn + j * 8 + 2 * (lane & 3);
                float v0 = acc[i][j][half * 2 + 0] + bias[c0];
                float v1 = acc[i][j][half * 2 + 1] + bias[c0 + 1];
                if (GELU) { v0 = gelu_exact(v0); v1 = gelu_exact(v1); }
                orow[c0]     = v0;
                orow[c0 + 1] = v1;
            }
        }
    }
}

// ---------------------------------------------------------------------------
// Launch
// ---------------------------------------------------------------------------
extern "C" void kernel_launch(void* const* d_in, const int* in_sizes, int n_in,
                              void* d_out, int out_size)
{
    const float* x  = (const float*)d_in[0];
    const float* Wg = (const float*)d_in[2];
    const float* W1 = (const float*)d_in[3];
    const float* b1 = (const float*)d_in[4];
    const float* W2 = (const float*)d_in[5];
    const float* b2 = (const float*)d_in[6];
    float* out = (float*)d_out;

    // 1) Gating + routing
    gate_kernel<<<BZ, 256>>>(x, Wg, out, out_size);
    route_build_kernel<<<1, 32>>>();

    // 2) h = gelu(x[n/2] @ W1[sel] + b1[sel])  (grouped by expert)
    //    grid: x = ntile (24), y = mtile (max 64), z = expert (8)
    moe_gemm<D_, DFF_, true, true, true, false>
        <<<dim3(DFF_ / 128, 64, E_), 128>>>(x, W1, b1, out);

    // 3) out = h @ W2[sel] + b2[sel]
    moe_gemm<DFF_, D_, false, false, false, true>
        <<<dim3(D_ / 128, 64, E_), 128>>>(x, W2, b2, out);
}

// round 4
// speedup vs baseline: 4.3921x; 1.1180x over previous
#include <cuda_runtime.h>
#include <cuda_bf16.h>
#include <math.h>

// Problem constants
#define BZ   128
#define T_   32
#define D_   768
#define DFF_ 3072
#define E_   8
#define BEAMS_ 2
#define NROWS (BZ * BEAMS_)                    // 256
#define OUT_ELEMS ((size_t)NROWS * T_ * D_)    // 6,291,456

// Scratch: h = gelu(x @ W1 + b1), 256 x 32 x 3072 fp32 = ~100 MB
__device__ __align__(256) float g_h[(size_t)NROWS * T_ * DFF_];
// Routing state
__device__ int g_sel[NROWS];
__device__ int g_cnt[E_];
__device__ int g_rows[E_][NROWS];

// ---------------------------------------------------------------------------
// Gating: mean-pool over T, logits = avg @ Wg, softmax, top-2 (stable ties)
// ---------------------------------------------------------------------------
__global__ void gate_kernel(const float* __restrict__ x,
                            const float* __restrict__ Wg,
                            float* __restrict__ out, int out_size)
{
    const int b = blockIdx.x;
    const int t = threadIdx.x;
    __shared__ float s_avg[D_];
    __shared__ float s_logits[E_];

    const float* xb = x + (size_t)b * T_ * D_;
    for (int d = t; d < D_; d += 256) {
        float s = 0.f;
        #pragma unroll
        for (int tt = 0; tt < T_; tt++) s += xb[tt * D_ + d];
        s_avg[d] = s * (1.0f / (float)T_);
    }
    __syncthreads();

    const int w = t >> 5, lane = t & 31;
    float p = 0.f;
    for (int d = lane; d < D_; d += 32) p += s_avg[d] * Wg[d * E_ + w];
    #pragma unroll
    for (int o = 16; o; o >>= 1) p += __shfl_xor_sync(0xffffffffu, p, o);
    if (lane == 0) s_logits[w] = p;
    __syncthreads();

    if (t == 0) {
        float mx = s_logits[0];
        #pragma unroll
        for (int e = 1; e < E_; e++) mx = fmaxf(mx, s_logits[e]);
        float pr[E_]; float se = 0.f;
        #pragma unroll
        for (int e = 0; e < E_; e++) { pr[e] = expf(s_logits[e] - mx); se += pr[e]; }
        float inv = 1.0f / se;
        #pragma unroll
        for (int e = 0; e < E_; e++) pr[e] *= inv;

        int i1 = 0;
        #pragma unroll
        for (int e = 1; e < E_; e++) if (pr[e] > pr[i1]) i1 = e;
        int i2 = -1;
        #pragma unroll
        for (int e = 0; e < E_; e++) {
            if (e == i1) continue;
            if (i2 < 0 || pr[e] > pr[i2]) i2 = e;
        }

        g_sel[2 * b + 0] = i1;
        g_sel[2 * b + 1] = i2;

        if (out_size >= (int)(OUT_ELEMS + 2 * NROWS)) {
            out[OUT_ELEMS + 2 * b + 0] = pr[i1];
            out[OUT_ELEMS + 2 * b + 1] = pr[i2];
            out[OUT_ELEMS + NROWS + 2 * b + 0] = (float)i1;
            out[OUT_ELEMS + NROWS + 2 * b + 1] = (float)i2;
        }
    }
}

__global__ void route_build_kernel()
{
    if (threadIdx.x == 0 && blockIdx.x == 0) {
        int cnt[E_];
        #pragma unroll
        for (int e = 0; e < E_; e++) cnt[e] = 0;
        for (int n = 0; n < NROWS; n++) {
            int e = g_sel[n];
            g_rows[e][cnt[e]++] = n;
        }
        #pragma unroll
        for (int e = 0; e < E_; e++) g_cnt[e] = cnt[e];
    }
}

// ---------------------------------------------------------------------------
// TF32 tensor-core grouped GEMM with cp.async double-buffered pipeline.
// Per block: 128x128 tile of O = act(A @ W[e] + b[e]) for expert e.
// 128 threads = 4 warps, each warp a 64x64 tile of m16n8k8 tf32 mma.
// Smem holds raw fp32 (cp.async 16B), cvt->tf32 at fragment load (same RNA
// rounding as before => numerics identical to the passing R2 kernel).
// ---------------------------------------------------------------------------
#define A_STRIDE 36     // floats per A row in smem (16B aligned, frag conflict-free)
#define B_STRIDE 136    // floats per B k-row in smem (16B aligned, frag conflict-free)
#define A_STAGE  (128 * A_STRIDE)
#define B_STAGE  (32 * B_STRIDE)
#define SMEM_FLOATS (2 * (A_STAGE + B_STAGE))
#define SMEM_BYTES  (SMEM_FLOATS * 4)          // 71,680 B

__device__ __forceinline__ unsigned f2tf(float f) {
    unsigned u;
    asm("cvt.rna.tf32.f32 %0, %1;" : "=r"(u) : "f"(f));
    return u;
}

__device__ __forceinline__ void mma_tf32(float* c, const unsigned* a, const unsigned* b) {
    asm volatile(
        "mma.sync.aligned.m16n8k8.row.col.f32.tf32.tf32.f32 "
        "{%0,%1,%2,%3}, {%4,%5,%6,%7}, {%8,%9}, {%0,%1,%2,%3};"
        : "+f"(c[0]), "+f"(c[1]), "+f"(c[2]), "+f"(c[3])
        : "r"(a[0]), "r"(a[1]), "r"(a[2]), "r"(a[3]), "r"(b[0]), "r"(b[1]));
}

__device__ __forceinline__ void cp_async16(float* smem_dst, const float* gmem_src) {
    unsigned s = (unsigned)__cvta_generic_to_shared(smem_dst);
    asm volatile("cp.async.cg.shared.global [%0], [%1], 16;\n" :: "r"(s), "l"(gmem_src));
}
__device__ __forceinline__ void cp_commit() {
    asm volatile("cp.async.commit_group;\n");
}
template <int N>
__device__ __forceinline__ void cp_wait() {
    asm volatile("cp.async.wait_group %0;\n" :: "n"(N));
}

__device__ __forceinline__ float gelu_exact(float v) {
    return 0.5f * v * (1.0f + erff(v * 0.70710678118654752f));
}

template <int KDIM, int NDIM, bool GELU, bool HALF_IN, bool OUT_GH, bool IN_GH>
__global__ __launch_bounds__(128)
void moe_gemm(const float* __restrict__ Aarg,
              const float* __restrict__ Wbase,
              const float* __restrict__ Bbase,
              float* __restrict__ Oarg)
{
    const int e     = blockIdx.z;
    const int cnt   = g_cnt[e];
    const int mtile = blockIdx.y;
    if (mtile * 4 >= cnt) return;
    const int ntile = blockIdx.x;

    extern __shared__ float sm[];
    float* As = sm;                 // [2][128][A_STRIDE]
    float* Bs = sm + 2 * A_STAGE;   // [2][32][B_STRIDE]
    __shared__ int s_rows[4];

    const int t = threadIdx.x;
    if (t < 4) {
        int idx = mtile * 4 + t;
        s_rows[t] = (idx < cnt) ? g_rows[e][idx] : -1;
    }
    __syncthreads();

    const float* A0   = IN_GH ? g_h : Aarg;
    const float* W    = Wbase + (size_t)e * KDIM * NDIM + (size_t)ntile * 128;
    const float* bias = Bbase + (size_t)e * NDIM + ntile * 128;

    const int warp = t >> 5, lane = t & 31;
    const int wm = (warp & 1) * 64;
    const int wn = (warp >> 1) * 64;

    float acc[4][8][4];
    #pragma unroll
    for (int i = 0; i < 4; i++)
        #pragma unroll
        for (int j = 0; j < 8; j++)
            #pragma unroll
            for (int q = 0; q < 4; q++) acc[i][j][q] = 0.f;

    // Precompute per-thread gmem pointers and smem offsets for the 16B chunks.
    // A tile: 128 rows x 32 k -> 1024 chunks, 8 per thread.
    const float* a_src[8];
    int a_dst[8];
    #pragma unroll
    for (int i = 0; i < 8; i++) {
        int lin = t + i * 128;
        int m   = lin >> 3;
        int kq  = lin & 7;
        int r   = s_rows[m >> 5];
        if (r < 0) r = s_rows[0];
        int arow = HALF_IN ? (r >> 1) : r;
        a_src[i] = A0 + ((size_t)arow * T_ + (m & 31)) * (size_t)KDIM + kq * 4;
        a_dst[i] = m * A_STRIDE + kq * 4;
    }
    // B tile: 32 k-rows x 128 cols -> 1024 chunks, 8 per thread.
    const float* b_src[8];
    int b_dst[8];
    #pragma unroll
    for (int i = 0; i < 8; i++) {
        int lin = t + i * 128;
        int kk  = lin >> 5;
        int jq  = lin & 31;
        b_src[i] = W + (size_t)kk * NDIM + jq * 4;
        b_dst[i] = kk * B_STRIDE + jq * 4;
    }

    const int iters = KDIM / 32;

    // Prologue: stage 0
    {
        #pragma unroll
        for (int i = 0; i < 8; i++) cp_async16(As + a_dst[i], a_src[i]);
        #pragma unroll
        for (int i = 0; i < 8; i++) cp_async16(Bs + b_dst[i], b_src[i]);
        cp_commit();
    }

    const int ar = lane >> 2, ac = lane & 3;

    for (int it = 0; it < iters; it++) {
        // Issue loads for stage it+1 into the other buffer
        if (it + 1 < iters) {
            int buf = (it + 1) & 1;
            int k0  = (it + 1) * 32;
            float* Ad = As + buf * A_STAGE;
            float* Bd = Bs + buf * B_STAGE;
            size_t boff = (size_t)k0 * NDIM;
            #pragma unroll
            for (int i = 0; i < 8; i++) cp_async16(Ad + a_dst[i], a_src[i] + k0);
            #pragma unroll
            for (int i = 0; i < 8; i++) cp_async16(Bd + b_dst[i], b_src[i] + boff);
        }
        cp_commit();
        cp_wait<1>();          // stage `it` resident
        __syncthreads();

        const float* Ab = As + (it & 1) * A_STAGE;
        const float* Bb = Bs + (it & 1) * B_STAGE;

        #pragma unroll
        for (int ks = 0; ks < 4; ks++) {
            const int kb = ks * 8;
            unsigned a[4][4], b[8][2];
            #pragma unroll
            for (int i = 0; i < 4; i++) {
                int row = wm + i * 16 + ar;
                a[i][0] = f2tf(Ab[row * A_STRIDE + kb + ac]);
                a[i][1] = f2tf(Ab[(row + 8) * A_STRIDE + kb + ac]);
                a[i][2] = f2tf(Ab[row * A_STRIDE + kb + ac + 4]);
                a[i][3] = f2tf(Ab[(row + 8) * A_STRIDE + kb + ac + 4]);
            }
            #pragma unroll
            for (int j = 0; j < 8; j++) {
                int col = wn + j * 8 + (lane >> 2);
                b[j][0] = f2tf(Bb[(kb + ac) * B_STRIDE + col]);
                b[j][1] = f2tf(Bb[(kb + ac + 4) * B_STRIDE + col]);
            }
            #pragma unroll
            for (int i = 0; i < 4; i++)
                #pragma unroll
                for (int j = 0; j < 8; j++)
                    mma_tf32(acc[i][j], a[i], b[j]);
        }
        __syncthreads();       // release buffer `it&1` before it is overwritten
    }

    // --- epilogue: bias (+GELU), scatter to gathered output rows ---
    #pragma unroll
    for (int i = 0; i < 4; i++) {
        int r0 = wm + i * 16 + (lane >> 2);
        #pragma unroll
        for (int half = 0; half < 2; half++) {
            int gm   = r0 + half * 8;
            int grow = s_rows[gm >> 5];
            if (grow < 0) continue;
            float* orow = (OUT_GH ? g_h : Oarg)
                        + ((size_t)grow * T_ + (gm & 31)) * (size_t)NDIM
                        + (size_t)ntile * 128;
            #pragma unroll
            for (int j = 0; j < 8; j++) {
                int c0 = wn + j * 8 + 2 * (lane & 3);
                float v0 = acc[i][j][half * 2 + 0] + bias[c0];
                float v1 = acc[i][j][half * 2 + 1] + bias[c0 + 1];
                if (GELU) { v0 = gelu_exact(v0); v1 = gelu_exact(v1); }
                orow[c0]     = v0;
                orow[c0 + 1] = v1;
            }
        }
    }
}

// ---------------------------------------------------------------------------
// Launch
// ---------------------------------------------------------------------------
extern "C" void kernel_launch(void* const* d_in, const int* in_sizes, int n_in,
                              void* d_out, int out_size)
{
    const float* x  = (const float*)d_in[0];
    const float* Wg = (const float*)d_in[2];
    const float* W1 = (const float*)d_in[3];
    const float* b1 = (const float*)d_in[4];
    const float* W2 = (const float*)d_in[5];
    const float* b2 = (const float*)d_in[6];
    float* out = (float*)d_out;

    // Opt-in to >48KB dynamic smem (idempotent; host-side, capture-safe)
    cudaFuncSetAttribute(moe_gemm<D_, DFF_, true, true, true, false>,
                         cudaFuncAttributeMaxDynamicSharedMemorySize, SMEM_BYTES);
    cudaFuncSetAttribute(moe_gemm<DFF_, D_, false, false, false, true>,
                         cudaFuncAttributeMaxDynamicSharedMemorySize, SMEM_BYTES);

    // 1) Gating + routing
    gate_kernel<<<BZ, 256>>>(x, Wg, out, out_size);
    route_build_kernel<<<1, 32>>>();

    // 2) h = gelu(x[n/2] @ W1[sel] + b1[sel])  (grouped by expert)
    moe_gemm<D_, DFF_, true, true, true, false>
        <<<dim3(DFF_ / 128, 64, E_), 128, SMEM_BYTES>>>(x, W1, b1, out);

    // 3) out = h @ W2[sel] + b2[sel]
    moe_gemm<DFF_, D_, false, false, false, true>
        <<<dim3(D_ / 128, 64, E_), 128, SMEM_BYTES>>>(x, W2, b2, out);
}

// round 5
// speedup vs baseline: 4.5718x; 1.0409x over previous
#include <cuda_runtime.h>
#include <cuda_bf16.h>
#include <math.h>

// Problem constants
#define BZ   128
#define T_   32
#define D_   768
#define DFF_ 3072
#define E_   8
#define BEAMS_ 2
#define NROWS (BZ * BEAMS_)                    // 256
#define OUT_ELEMS ((size_t)NROWS * T_ * D_)    // 6,291,456

// Scratch: h = gelu(x @ W1 + b1), 256 x 32 x 3072 fp32 = ~100 MB
__device__ __align__(256) float g_h[(size_t)NROWS * T_ * DFF_];
// Routing state
__device__ int g_sel[NROWS];
__device__ int g_cnt[E_];
__device__ int g_rows[E_][NROWS];

// ---------------------------------------------------------------------------
// Gating: mean-pool over T, logits = avg @ Wg, softmax, top-2 (stable ties)
// ---------------------------------------------------------------------------
__global__ void gate_kernel(const float* __restrict__ x,
                            const float* __restrict__ Wg,
                            float* __restrict__ out, int out_size)
{
    const int b = blockIdx.x;
    const int t = threadIdx.x;
    __shared__ float s_avg[D_];
    __shared__ float s_logits[E_];

    const float* xb = x + (size_t)b * T_ * D_;
    for (int d = t; d < D_; d += 256) {
        float s = 0.f;
        #pragma unroll
        for (int tt = 0; tt < T_; tt++) s += xb[tt * D_ + d];
        s_avg[d] = s * (1.0f / (float)T_);
    }
    __syncthreads();

    const int w = t >> 5, lane = t & 31;
    float p = 0.f;
    for (int d = lane; d < D_; d += 32) p += s_avg[d] * Wg[d * E_ + w];
    #pragma unroll
    for (int o = 16; o; o >>= 1) p += __shfl_xor_sync(0xffffffffu, p, o);
    if (lane == 0) s_logits[w] = p;
    __syncthreads();

    if (t == 0) {
        float mx = s_logits[0];
        #pragma unroll
        for (int e = 1; e < E_; e++) mx = fmaxf(mx, s_logits[e]);
        float pr[E_]; float se = 0.f;
        #pragma unroll
        for (int e = 0; e < E_; e++) { pr[e] = expf(s_logits[e] - mx); se += pr[e]; }
        float inv = 1.0f / se;
        #pragma unroll
        for (int e = 0; e < E_; e++) pr[e] *= inv;

        int i1 = 0;
        #pragma unroll
        for (int e = 1; e < E_; e++) if (pr[e] > pr[i1]) i1 = e;
        int i2 = -1;
        #pragma unroll
        for (int e = 0; e < E_; e++) {
            if (e == i1) continue;
            if (i2 < 0 || pr[e] > pr[i2]) i2 = e;
        }

        g_sel[2 * b + 0] = i1;
        g_sel[2 * b + 1] = i2;

        if (out_size >= (int)(OUT_ELEMS + 2 * NROWS)) {
            out[OUT_ELEMS + 2 * b + 0] = pr[i1];
            out[OUT_ELEMS + 2 * b + 1] = pr[i2];
            out[OUT_ELEMS + NROWS + 2 * b + 0] = (float)i1;
            out[OUT_ELEMS + NROWS + 2 * b + 1] = (float)i2;
        }
    }
}

__global__ void route_build_kernel()
{
    if (threadIdx.x == 0 && blockIdx.x == 0) {
        int cnt[E_];
        #pragma unroll
        for (int e = 0; e < E_; e++) cnt[e] = 0;
        for (int n = 0; n < NROWS; n++) {
            int e = g_sel[n];
            g_rows[e][cnt[e]++] = n;
        }
        #pragma unroll
        for (int e = 0; e < E_; e++) g_cnt[e] = cnt[e];
    }
}

// ---------------------------------------------------------------------------
// TF32 tensor-core grouped GEMM, cp.async double-buffered, 8 warps/block.
// Per block: 128x128 tile of O = act(A @ W[e] + b[e]) for expert e.
// 256 threads = 8 warps in a 4(m) x 2(n) grid; warp tile 32x64 (m16n8k8).
// Fragment loads: RNA cvt to tf32 (numerically identical to R2/R3).
// ---------------------------------------------------------------------------
#define A_STRIDE 36     // floats per A row in smem (16B aligned, frag conflict-free)
#define B_STRIDE 136    // floats per B k-row in smem (16B aligned, frag conflict-free)
#define A_STAGE  (128 * A_STRIDE)
#define B_STAGE  (32 * B_STRIDE)
#define SMEM_FLOATS (2 * (A_STAGE + B_STAGE))
#define SMEM_BYTES  (SMEM_FLOATS * 4)          // 71,680 B

__device__ __forceinline__ unsigned f2tf(float f) {
    unsigned u;
    asm("cvt.rna.tf32.f32 %0, %1;" : "=r"(u) : "f"(f));
    return u;
}

__device__ __forceinline__ void mma_tf32(float* c, const unsigned* a, const unsigned* b) {
    asm volatile(
        "mma.sync.aligned.m16n8k8.row.col.f32.tf32.tf32.f32 "
        "{%0,%1,%2,%3}, {%4,%5,%6,%7}, {%8,%9}, {%0,%1,%2,%3};"
        : "+f"(c[0]), "+f"(c[1]), "+f"(c[2]), "+f"(c[3])
        : "r"(a[0]), "r"(a[1]), "r"(a[2]), "r"(a[3]), "r"(b[0]), "r"(b[1]));
}

__device__ __forceinline__ void cp_async16(float* smem_dst, const float* gmem_src) {
    unsigned s = (unsigned)__cvta_generic_to_shared(smem_dst);
    asm volatile("cp.async.cg.shared.global [%0], [%1], 16;\n" :: "r"(s), "l"(gmem_src));
}
__device__ __forceinline__ void cp_commit() {
    asm volatile("cp.async.commit_group;\n");
}
template <int N>
__device__ __forceinline__ void cp_wait() {
    asm volatile("cp.async.wait_group %0;\n" :: "n"(N));
}

__device__ __forceinline__ float gelu_exact(float v) {
    return 0.5f * v * (1.0f + erff(v * 0.70710678118654752f));
}

template <int KDIM, int NDIM, bool GELU, bool HALF_IN, bool OUT_GH, bool IN_GH>
__global__ __launch_bounds__(256, 2)
void moe_gemm(const float* __restrict__ Aarg,
              const float* __restrict__ Wbase,
              const float* __restrict__ Bbase,
              float* __restrict__ Oarg)
{
    const int e     = blockIdx.z;
    const int cnt   = g_cnt[e];
    const int mtile = blockIdx.y;
    if (mtile * 4 >= cnt) return;
    const int ntile = blockIdx.x;

    extern __shared__ float sm[];
    float* As = sm;                 // [2][128][A_STRIDE]
    float* Bs = sm + 2 * A_STAGE;   // [2][32][B_STRIDE]
    __shared__ int s_rows[4];

    const int t = threadIdx.x;      // 0..255
    if (t < 4) {
        int idx = mtile * 4 + t;
        s_rows[t] = (idx < cnt) ? g_rows[e][idx] : -1;
    }
    __syncthreads();

    const float* A0   = IN_GH ? g_h : Aarg;
    const float* W    = Wbase + (size_t)e * KDIM * NDIM + (size_t)ntile * 128;
    const float* bias = Bbase + (size_t)e * NDIM + ntile * 128;

    const int warp = t >> 5, lane = t & 31;
    const int wm = (warp & 3) * 32;         // 4 warps along m
    const int wn = (warp >> 2) * 64;        // 2 warps along n

    float acc[2][8][4];
    #pragma unroll
    for (int i = 0; i < 2; i++)
        #pragma unroll
        for (int j = 0; j < 8; j++)
            #pragma unroll
            for (int q = 0; q < 4; q++) acc[i][j][q] = 0.f;

    // Per-thread cp.async chunks: A tile 128x32 -> 1024 16B chunks, 4/thread.
    const float* a_src[4];
    int a_dst[4];
    #pragma unroll
    for (int i = 0; i < 4; i++) {
        int lin = t + i * 256;
        int m   = lin >> 3;
        int kq  = lin & 7;
        int r   = s_rows[m >> 5];
        if (r < 0) r = s_rows[0];
        int arow = HALF_IN ? (r >> 1) : r;
        a_src[i] = A0 + ((size_t)arow * T_ + (m & 31)) * (size_t)KDIM + kq * 4;
        a_dst[i] = m * A_STRIDE + kq * 4;
    }
    // B tile 32x128 -> 1024 chunks, 4/thread.
    const float* b_src[4];
    int b_dst[4];
    #pragma unroll
    for (int i = 0; i < 4; i++) {
        int lin = t + i * 256;
        int kk  = lin >> 5;
        int jq  = lin & 31;
        b_src[i] = W + (size_t)kk * NDIM + jq * 4;
        b_dst[i] = kk * B_STRIDE + jq * 4;
    }

    const int iters = KDIM / 32;

    // Prologue: stage 0
    {
        #pragma unroll
        for (int i = 0; i < 4; i++) cp_async16(As + a_dst[i], a_src[i]);
        #pragma unroll
        for (int i = 0; i < 4; i++) cp_async16(Bs + b_dst[i], b_src[i]);
        cp_commit();
    }

    const int ar = lane >> 2, ac = lane & 3;

    for (int it = 0; it < iters; it++) {
        if (it + 1 < iters) {
            int buf = (it + 1) & 1;
            int k0  = (it + 1) * 32;
            float* Ad = As + buf * A_STAGE;
            float* Bd = Bs + buf * B_STAGE;
            size_t boff = (size_t)k0 * NDIM;
            #pragma unroll
            for (int i = 0; i < 4; i++) cp_async16(Ad + a_dst[i], a_src[i] + k0);
            #pragma unroll
            for (int i = 0; i < 4; i++) cp_async16(Bd + b_dst[i], b_src[i] + boff);
        }
        cp_commit();
        cp_wait<1>();
        __syncthreads();

        const float* Ab = As + (it & 1) * A_STAGE;
        const float* Bb = Bs + (it & 1) * B_STAGE;

        #pragma unroll
        for (int ks = 0; ks < 4; ks++) {
            const int kb = ks * 8;
            unsigned a[2][4], b[8][2];
            #pragma unroll
            for (int i = 0; i < 2; i++) {
                int row = wm + i * 16 + ar;
                a[i][0] = f2tf(Ab[row * A_STRIDE + kb + ac]);
                a[i][1] = f2tf(Ab[(row + 8) * A_STRIDE + kb + ac]);
                a[i][2] = f2tf(Ab[row * A_STRIDE + kb + ac + 4]);
                a[i][3] = f2tf(Ab[(row + 8) * A_STRIDE + kb + ac + 4]);
            }
            #pragma unroll
            for (int j = 0; j < 8; j++) {
                int col = wn + j * 8 + (lane >> 2);
                b[j][0] = f2tf(Bb[(kb + ac) * B_STRIDE + col]);
                b[j][1] = f2tf(Bb[(kb + ac + 4) * B_STRIDE + col]);
            }
            #pragma unroll
            for (int i = 0; i < 2; i++)
                #pragma unroll
                for (int j = 0; j < 8; j++)
                    mma_tf32(acc[i][j], a[i], b[j]);
        }
        __syncthreads();
    }

    // --- epilogue: bias (+GELU), scatter to gathered output rows ---
    #pragma unroll
    for (int i = 0; i < 2; i++) {
        int r0 = wm + i * 16 + (lane >> 2);
        #pragma unroll
        for (int half = 0; half < 2; half++) {
            int gm   = r0 + half * 8;
            int grow = s_rows[gm >> 5];
            if (grow < 0) continue;
            float* orow = (OUT_GH ? g_h : Oarg)
                        + ((size_t)grow * T_ + (gm & 31)) * (size_t)NDIM
                        + (size_t)ntile * 128;
            #pragma unroll
            for (int j = 0; j < 8; j++) {
                int c0 = wn + j * 8 + 2 * (lane & 3);
                float v0 = acc[i][j][half * 2 + 0] + bias[c0];
                float v1 = acc[i][j][half * 2 + 1] + bias[c0 + 1];
                if (GELU) { v0 = gelu_exact(v0); v1 = gelu_exact(v1); }
                orow[c0]     = v0;
                orow[c0 + 1] = v1;
            }
        }
    }
}

// ---------------------------------------------------------------------------
// Launch
// ---------------------------------------------------------------------------
extern "C" void kernel_launch(void* const* d_in, const int* in_sizes, int n_in,
                              void* d_out, int out_size)
{
    const float* x  = (const float*)d_in[0];
    const float* Wg = (const float*)d_in[2];
    const float* W1 = (const float*)d_in[3];
    const float* b1 = (const float*)d_in[4];
    const float* W2 = (const float*)d_in[5];
    const float* b2 = (const float*)d_in[6];
    float* out = (float*)d_out;

    cudaFuncSetAttribute(moe_gemm<D_, DFF_, true, true, true, false>,
                         cudaFuncAttributeMaxDynamicSharedMemorySize, SMEM_BYTES);
    cudaFuncSetAttribute(moe_gemm<DFF_, D_, false, false, false, true>,
                         cudaFuncAttributeMaxDynamicSharedMemorySize, SMEM_BYTES);

    // 1) Gating + routing
    gate_kernel<<<BZ, 256>>>(x, Wg, out, out_size);
    route_build_kernel<<<1, 32>>>();

    // 2) h = gelu(x[n/2] @ W1[sel] + b1[sel])  (grouped by expert)
    moe_gemm<D_, DFF_, true, true, true, false>
        <<<dim3(DFF_ / 128, 64, E_), 256, SMEM_BYTES>>>(x, W1, b1, out);

    // 3) out = h @ W2[sel] + b2[sel]
    moe_gemm<DFF_, D_, false, false, false, true>
        <<<dim3(D_ / 128, 64, E_), 256, SMEM_BYTES>>>(x, W2, b2, out);
}